// round 1
// baseline (speedup 1.0000x reference)
#include <cuda_runtime.h>
#include <math.h>
#include <stdint.h>

// ---------------- problem constants ----------------
#define B_    2
#define S_    2048
#define HID_  2048
#define IN_   4096
#define H_    16
#define NOPE_ 128
#define ROPE_ 64
#define VHD_  128
#define QKD_  192        // NOPE+ROPE
#define QR_   1536
#define KVR_  512
#define TOK_  (B_*S_)    // 4096
#define BH_   (B_*H_)    // 32
#define EPS_  1e-6f

// ---------------- scratch (device globals; no allocs allowed) ----------------
__device__ float g_qa [TOK_*QR_];                 // hidden @ Wq_a (rms in-place)
__device__ float g_q  [TOK_*(H_*QKD_)];           // q_a_rms @ Wq_b
__device__ float g_kvc[TOK_*(KVR_+ROPE_)];        // hidden @ Wkv_a
__device__ float g_kvn[TOK_*KVR_];                // rms(kv_comp)
__device__ float g_kv [TOK_*(H_*(NOPE_+VHD_))];   // kvn @ Wkv_b
__device__ float g_Qf [BH_*S_*QKD_];              // q_full, [bh][s][192]
__device__ float g_Kf [BH_*S_*QKD_];              // k_full, [bh][s][192]
__device__ float g_Vf [BH_*S_*VHD_];              // v,      [bh][s][128]
__device__ float g_Sc [(size_t)BH_*S_*S_];        // scores/attn, 512MB
__device__ float g_ctx[TOK_*(H_*VHD_)];           // attention output [tok][2048]

// ---------------- generic tiled SGEMM: C = alpha * A[M,K] @ B[K,N] ----------------
#define BM 128
#define BN 128
#define BK 8
#define TM 8
#define TN 8

__global__ __launch_bounds__(256) void gemm_nn(const float* __restrict__ A,
                                               const float* __restrict__ Bm,
                                               float* __restrict__ C,
                                               int M, int N, int K, float alpha)
{
    __shared__ float As[BK][BM];
    __shared__ float Bs[BK][BN];
    const int tid = threadIdx.x;

    const int aRow = tid >> 1;            // 0..127
    const int aCol = (tid & 1) << 2;      // 0 or 4
    const int bRow = tid >> 5;            // 0..7
    const int bCol = (tid & 31) << 2;     // 0..124

    const float* Aptr = A + (size_t)(blockIdx.y * BM + aRow) * K + aCol;
    const float* Bptr = Bm + (size_t)bRow * N + (size_t)blockIdx.x * BN + bCol;
    const bool bInB = (blockIdx.x * BN + bCol) < N;   // N % 4 == 0 always

    const int tr = (tid >> 4) * TM;
    const int tc = (tid & 15) * TN;

    float acc[TM][TN];
    #pragma unroll
    for (int i = 0; i < TM; i++)
        #pragma unroll
        for (int j = 0; j < TN; j++) acc[i][j] = 0.f;

    for (int k0 = 0; k0 < K; k0 += BK) {
        float4 av = *(const float4*)Aptr;
        As[aCol+0][aRow] = av.x; As[aCol+1][aRow] = av.y;
        As[aCol+2][aRow] = av.z; As[aCol+3][aRow] = av.w;
        float4 bv = make_float4(0.f,0.f,0.f,0.f);
        if (bInB) bv = *(const float4*)Bptr;
        *(float4*)&Bs[bRow][bCol] = bv;
        __syncthreads();

        #pragma unroll
        for (int k = 0; k < BK; k++) {
            float4 a0 = *(const float4*)&As[k][tr];
            float4 a1 = *(const float4*)&As[k][tr+4];
            float4 b0 = *(const float4*)&Bs[k][tc];
            float4 b1 = *(const float4*)&Bs[k][tc+4];
            float am[8] = {a0.x,a0.y,a0.z,a0.w,a1.x,a1.y,a1.z,a1.w};
            float bn[8] = {b0.x,b0.y,b0.z,b0.w,b1.x,b1.y,b1.z,b1.w};
            #pragma unroll
            for (int i = 0; i < TM; i++)
                #pragma unroll
                for (int j = 0; j < TN; j++)
                    acc[i][j] += am[i] * bn[j];
        }
        __syncthreads();
        Aptr += BK;
        Bptr += (size_t)BK * N;
    }

    const int rowBase = blockIdx.y * BM + tr;
    const int colBase = blockIdx.x * BN + tc;
    #pragma unroll
    for (int i = 0; i < TM; i++) {
        #pragma unroll
        for (int j = 0; j < TN; j += 4) {
            int col = colBase + j;
            if (col < N) {
                float4 o = make_float4(acc[i][j]*alpha, acc[i][j+1]*alpha,
                                       acc[i][j+2]*alpha, acc[i][j+3]*alpha);
                *(float4*)&C[(size_t)(rowBase + i) * N + col] = o;
            }
        }
    }
}

// --------- batched scores: Sc[bh] = scale * Qf[bh] @ Kf[bh]^T  (causal skip) ---------
__global__ __launch_bounds__(256) void scores_nt(float scale)
{
    // fully-masked blocks: min col in block > max row in block
    if (blockIdx.x * BN >= blockIdx.y * BM + BM) return;

    const int bh = blockIdx.z;
    const float* A  = g_Qf + (size_t)bh * S_ * QKD_;
    const float* Bm = g_Kf + (size_t)bh * S_ * QKD_;
    float* C = g_Sc + (size_t)bh * S_ * S_;

    __shared__ float As[BK][BM];
    __shared__ float Bs[BK][BN];
    const int tid = threadIdx.x;

    const int aRow = tid >> 1;
    const int aCol = (tid & 1) << 2;
    const float* Aptr = A  + (size_t)(blockIdx.y * BM + aRow) * QKD_ + aCol;
    const float* Bptr = Bm + (size_t)(blockIdx.x * BN + aRow) * QKD_ + aCol;

    const int tr = (tid >> 4) * TM;
    const int tc = (tid & 15) * TN;

    float acc[TM][TN];
    #pragma unroll
    for (int i = 0; i < TM; i++)
        #pragma unroll
        for (int j = 0; j < TN; j++) acc[i][j] = 0.f;

    for (int k0 = 0; k0 < QKD_; k0 += BK) {
        float4 av = *(const float4*)Aptr;
        As[aCol+0][aRow] = av.x; As[aCol+1][aRow] = av.y;
        As[aCol+2][aRow] = av.z; As[aCol+3][aRow] = av.w;
        float4 bv = *(const float4*)Bptr;
        Bs[aCol+0][aRow] = bv.x; Bs[aCol+1][aRow] = bv.y;
        Bs[aCol+2][aRow] = bv.z; Bs[aCol+3][aRow] = bv.w;
        __syncthreads();

        #pragma unroll
        for (int k = 0; k < BK; k++) {
            float4 a0 = *(const float4*)&As[k][tr];
            float4 a1 = *(const float4*)&As[k][tr+4];
            float4 b0 = *(const float4*)&Bs[k][tc];
            float4 b1 = *(const float4*)&Bs[k][tc+4];
            float am[8] = {a0.x,a0.y,a0.z,a0.w,a1.x,a1.y,a1.z,a1.w};
            float bn[8] = {b0.x,b0.y,b0.z,b0.w,b1.x,b1.y,b1.z,b1.w};
            #pragma unroll
            for (int i = 0; i < TM; i++)
                #pragma unroll
                for (int j = 0; j < TN; j++)
                    acc[i][j] += am[i] * bn[j];
        }
        __syncthreads();
        Aptr += BK;
        Bptr += BK;
    }

    const int rowBase = blockIdx.y * BM + tr;
    const int colBase = blockIdx.x * BN + tc;
    #pragma unroll
    for (int i = 0; i < TM; i++)
        #pragma unroll
        for (int j = 0; j < TN; j += 4) {
            float4 o = make_float4(acc[i][j]*scale, acc[i][j+1]*scale,
                                   acc[i][j+2]*scale, acc[i][j+3]*scale);
            *(float4*)&C[(size_t)(rowBase + i) * S_ + colBase + j] = o;
        }
}

// --------- batched PV: ctx += attn[bh][S,S] @ V[bh][S,128]  (causal K-limit) ---------
__global__ __launch_bounds__(256) void pv_gemm()
{
    const int bh = blockIdx.z;
    const int b = bh / H_, h = bh % H_;
    const float* A  = g_Sc + (size_t)bh * S_ * S_;
    const float* Bm = g_Vf + (size_t)bh * S_ * VHD_;

    __shared__ float As[BK][BM];
    __shared__ float Bs[BK][BN];
    const int tid = threadIdx.x;

    const int aRow = tid >> 1;
    const int aCol = (tid & 1) << 2;
    const int bRow = tid >> 5;
    const int bCol = (tid & 31) << 2;    // 0..124, N = 128

    const float* Aptr = A + (size_t)(blockIdx.y * BM + aRow) * S_ + aCol;
    const float* Bptr = Bm + (size_t)bRow * VHD_ + bCol;

    const int tr = (tid >> 4) * TM;
    const int tc = (tid & 15) * TN;

    float acc[TM][TN];
    #pragma unroll
    for (int i = 0; i < TM; i++)
        #pragma unroll
        for (int j = 0; j < TN; j++) acc[i][j] = 0.f;

    const int Kmax = blockIdx.y * BM + BM;   // keys beyond max row are zero
    for (int k0 = 0; k0 < Kmax; k0 += BK) {
        float4 av = *(const float4*)Aptr;
        As[aCol+0][aRow] = av.x; As[aCol+1][aRow] = av.y;
        As[aCol+2][aRow] = av.z; As[aCol+3][aRow] = av.w;
        float4 bv = *(const float4*)Bptr;
        *(float4*)&Bs[bRow][bCol] = bv;
        __syncthreads();

        #pragma unroll
        for (int k = 0; k < BK; k++) {
            float4 a0 = *(const float4*)&As[k][tr];
            float4 a1 = *(const float4*)&As[k][tr+4];
            float4 b0 = *(const float4*)&Bs[k][tc];
            float4 b1 = *(const float4*)&Bs[k][tc+4];
            float am[8] = {a0.x,a0.y,a0.z,a0.w,a1.x,a1.y,a1.z,a1.w};
            float bn[8] = {b0.x,b0.y,b0.z,b0.w,b1.x,b1.y,b1.z,b1.w};
            #pragma unroll
            for (int i = 0; i < TM; i++)
                #pragma unroll
                for (int j = 0; j < TN; j++)
                    acc[i][j] += am[i] * bn[j];
        }
        __syncthreads();
        Aptr += BK;
        Bptr += (size_t)BK * VHD_;
    }

    const int rowBase = blockIdx.y * BM + tr;
    #pragma unroll
    for (int i = 0; i < TM; i++)
        #pragma unroll
        for (int j = 0; j < TN; j += 4) {
            float4 o = make_float4(acc[i][j], acc[i][j+1], acc[i][j+2], acc[i][j+3]);
            size_t off = (size_t)(b * S_ + rowBase + i) * (H_*VHD_) + h * VHD_ + tc + j;
            *(float4*)&g_ctx[off] = o;
        }
}

// ---------------- block reductions ----------------
__device__ __forceinline__ float block_reduce_max(float v, float* sbuf) {
    int tid = threadIdx.x;
    sbuf[tid] = v; __syncthreads();
    #pragma unroll
    for (int s = 128; s > 0; s >>= 1) {
        if (tid < s) sbuf[tid] = fmaxf(sbuf[tid], sbuf[tid + s]);
        __syncthreads();
    }
    float r = sbuf[0]; __syncthreads();
    return r;
}
__device__ __forceinline__ float block_reduce_sum(float v, float* sbuf) {
    int tid = threadIdx.x;
    sbuf[tid] = v; __syncthreads();
    #pragma unroll
    for (int s = 128; s > 0; s >>= 1) {
        if (tid < s) sbuf[tid] = sbuf[tid] + sbuf[tid + s];
        __syncthreads();
    }
    float r = sbuf[0]; __syncthreads();
    return r;
}

// ---------------- rmsnorm: y = x * rsqrt(mean(x^2)+eps) * w  (first n of each row) ----------------
__global__ __launch_bounds__(256) void rmsnorm_kernel(const float* __restrict__ x,
                                                      const float* __restrict__ w,
                                                      float* __restrict__ y,
                                                      int n, int si, int so)
{
    __shared__ float sbuf[256];
    const size_t row = blockIdx.x;
    const float* xr = x + row * si;
    float acc = 0.f;
    for (int j = threadIdx.x; j < n; j += 256) { float v = xr[j]; acc += v * v; }
    float tot = block_reduce_sum(acc, sbuf);
    float scale = rsqrtf(tot / (float)n + EPS_);
    float* yr = y + row * so;
    for (int j = threadIdx.x; j < n; j += 256) yr[j] = xr[j] * scale * w[j];
}

// ---------------- RoPE helpers + assembly ----------------
__device__ __forceinline__ float rope_val(const float* pair_base, int drel, float pos) {
    // drel in [0,64): interleaved rope on a 64-vector starting at pair_base
    int j = drel >> 1;
    float inv = powf(10000.f, -((float)(2 * j)) / 64.f);
    float ang = pos * inv;
    float c = cosf(ang), s = sinf(ang);
    float ev = pair_base[2*j], ov = pair_base[2*j + 1];
    return ((drel & 1) == 0) ? (ev * c - ov * s) : (ov * c + ev * s);
}

__global__ void build_q(const int* __restrict__ pos) {
    int idx = blockIdx.x * blockDim.x + threadIdx.x;
    if (idx >= BH_ * S_ * QKD_) return;
    int d  = idx % QKD_;
    int r  = idx / QKD_;
    int s  = r % S_;
    int bh = r / S_;
    int b = bh / H_, h = bh % H_;
    int tok = b * S_ + s;
    const float* src = g_q + (size_t)tok * (H_*QKD_) + h * QKD_;
    float v;
    if (d < NOPE_) v = src[d];
    else           v = rope_val(src + NOPE_, d - NOPE_, (float)pos[tok]);
    g_Qf[idx] = v;
}

__global__ void build_k(const int* __restrict__ pos) {
    int idx = blockIdx.x * blockDim.x + threadIdx.x;
    if (idx >= BH_ * S_ * QKD_) return;
    int d  = idx % QKD_;
    int r  = idx / QKD_;
    int s  = r % S_;
    int bh = r / S_;
    int b = bh / H_, h = bh % H_;
    int tok = b * S_ + s;
    float v;
    if (d < NOPE_) v = g_kv[(size_t)tok * (H_*(NOPE_+VHD_)) + h * (NOPE_+VHD_) + d];
    else           v = rope_val(g_kvc + (size_t)tok * (KVR_+ROPE_) + KVR_,
                                d - NOPE_, (float)pos[tok]);
    g_Kf[idx] = v;
}

__global__ void build_v() {
    int idx = blockIdx.x * blockDim.x + threadIdx.x;
    if (idx >= BH_ * S_ * VHD_) return;
    int d  = idx % VHD_;
    int r  = idx / VHD_;
    int s  = r % S_;
    int bh = r / S_;
    int b = bh / H_, h = bh % H_;
    int tok = b * S_ + s;
    g_Vf[idx] = g_kv[(size_t)tok * (H_*(NOPE_+VHD_)) + h * (NOPE_+VHD_) + NOPE_ + d];
}

// ---------------- causal softmax (row-wise, zero out masked) ----------------
__global__ __launch_bounds__(256) void softmax_causal() {
    __shared__ float sbuf[256];
    const int row = blockIdx.x;        // bh*S + q
    const int q = row % S_;
    float* p = g_Sc + (size_t)row * S_;
    const int n = q + 1;

    float m = -INFINITY;
    for (int j = threadIdx.x; j < n; j += 256) m = fmaxf(m, p[j]);
    m = block_reduce_max(m, sbuf);

    float acc = 0.f;
    for (int j = threadIdx.x; j < n; j += 256) {
        float e = expf(p[j] - m);
        p[j] = e;
        acc += e;
    }
    float tot = block_reduce_sum(acc, sbuf);
    float inv = 1.f / tot;
    for (int j = threadIdx.x; j < n; j += 256) p[j] *= inv;
    for (int j = n + threadIdx.x; j < S_; j += 256) p[j] = 0.f;
}

// ---------------- launcher ----------------
extern "C" void kernel_launch(void* const* d_in, const int* in_sizes, int n_in,
                              void* d_out, int out_size)
{
    const float* hs    = (const float*)d_in[0];
    const float* Wq_a  = (const float*)d_in[1];
    const float* q_ln  = (const float*)d_in[2];
    const float* Wq_b  = (const float*)d_in[3];
    const float* Wkv_a = (const float*)d_in[4];
    const float* kv_ln = (const float*)d_in[5];
    const float* Wkv_b = (const float*)d_in[6];
    const float* Wo    = (const float*)d_in[7];
    const int*   pos   = (const int*)  d_in[8];
    float* out = (float*)d_out;

    float *p_qa, *p_q, *p_kvc, *p_kvn, *p_kv, *p_ctx;
    cudaGetSymbolAddress((void**)&p_qa,  g_qa);
    cudaGetSymbolAddress((void**)&p_q,   g_q);
    cudaGetSymbolAddress((void**)&p_kvc, g_kvc);
    cudaGetSymbolAddress((void**)&p_kvn, g_kvn);
    cudaGetSymbolAddress((void**)&p_kv,  g_kv);
    cudaGetSymbolAddress((void**)&p_ctx, g_ctx);

    // q path
    gemm_nn<<<dim3(QR_/BN, TOK_/BM), 256>>>(hs, Wq_a, p_qa, TOK_, QR_, IN_, 1.f);
    rmsnorm_kernel<<<TOK_, 256>>>(p_qa, q_ln, p_qa, QR_, QR_, QR_);
    gemm_nn<<<dim3((H_*QKD_)/BN, TOK_/BM), 256>>>(p_qa, Wq_b, p_q, TOK_, H_*QKD_, QR_, 1.f);

    // kv path
    gemm_nn<<<dim3((KVR_+ROPE_+BN-1)/BN, TOK_/BM), 256>>>(hs, Wkv_a, p_kvc,
                                                          TOK_, KVR_+ROPE_, IN_, 1.f);
    rmsnorm_kernel<<<TOK_, 256>>>(p_kvc, kv_ln, p_kvn, KVR_, KVR_+ROPE_, KVR_);
    gemm_nn<<<dim3((H_*(NOPE_+VHD_))/BN, TOK_/BM), 256>>>(p_kvn, Wkv_b, p_kv,
                                                          TOK_, H_*(NOPE_+VHD_), KVR_, 1.f);

    // assemble Q/K (with RoPE) and V
    int nq = BH_ * S_ * QKD_;
    build_q<<<(nq + 255) / 256, 256>>>(pos);
    build_k<<<(nq + 255) / 256, 256>>>(pos);
    int nv = BH_ * S_ * VHD_;
    build_v<<<(nv + 255) / 256, 256>>>();

    // attention
    float scale = 1.f / sqrtf((float)QKD_);
    scores_nt<<<dim3(S_/BN, S_/BM, BH_), 256>>>(scale);
    softmax_causal<<<BH_ * S_, 256>>>();
    pv_gemm<<<dim3(1, S_/BM, BH_), 256>>>();

    // output projection
    gemm_nn<<<dim3(HID_/BN, TOK_/BM), 256>>>(p_ctx, Wo, out, TOK_, HID_, HID_, 1.f);
}

// round 2
// speedup vs baseline: 2.5295x; 2.5295x over previous
#include <cuda_runtime.h>
#include <math.h>
#include <stdint.h>

// ---------------- problem constants ----------------
#define B_    2
#define S_    2048
#define HID_  2048
#define IN_   4096
#define H_    16
#define NOPE_ 128
#define ROPE_ 64
#define VHD_  128
#define QKD_  192
#define QR_   1536
#define KVR_  512
#define TOK_  (B_*S_)
#define BH_   (B_*H_)
#define EPS_  1e-6f

// ---------------- scratch ----------------
__device__ float g_qa [TOK_*QR_];
__device__ float g_q  [TOK_*(H_*QKD_)];
__device__ float g_kvc[TOK_*(KVR_+ROPE_)];
__device__ float g_kvn[TOK_*KVR_];
__device__ float g_kv [TOK_*(H_*(NOPE_+VHD_))];
__device__ float g_Qf [BH_*S_*QKD_];
__device__ float g_Kf [BH_*S_*QKD_];
__device__ float g_Vf [BH_*S_*VHD_];
__device__ float g_Sc [(size_t)BH_*S_*S_];
__device__ float g_ctx[TOK_*(H_*VHD_)];

// ---------------- tf32 helpers ----------------
__device__ __forceinline__ uint32_t f2tf32(float x) {
    uint32_t u;
    asm("cvt.rna.tf32.f32 %0, %1;" : "=r"(u) : "f"(x));
    return u;
}
__device__ __forceinline__ void mma_tf32(float c[4], const uint32_t a[4], const uint32_t b[2]) {
    asm volatile(
        "mma.sync.aligned.m16n8k8.row.col.f32.tf32.tf32.f32 "
        "{%0,%1,%2,%3}, {%4,%5,%6,%7}, {%8,%9}, {%0,%1,%2,%3};"
        : "+f"(c[0]), "+f"(c[1]), "+f"(c[2]), "+f"(c[3])
        : "r"(a[0]), "r"(a[1]), "r"(a[2]), "r"(a[3]), "r"(b[0]), "r"(b[1]));
}

// ---------------- tf32 tensor-core GEMM ----------------
// C[M,N] = alpha * A[M,K] @ op(B),  op(B) = B[K,N] (TB=0) or B[N,K]^T (TB=1)
// Tiles: 128x128, BK=16; 8 warps, each warp 64(M) x 32(N) via 4x4 m16n8k8 frags.
#define GBM 128
#define GBN 128
#define GBK 16
#define LDW 136   // padded smem row (words); 136%32==8 -> conflict-free frag LDS

template<bool TB, bool CAUSAL, bool PV>
__global__ __launch_bounds__(256) void mma_gemm(
    const float* __restrict__ A, const float* __restrict__ B, float* __restrict__ C,
    int M, int N, int K, int lda, int ldb, int ldc,
    size_t sA, size_t sB, size_t sC, float alpha)
{
    if (CAUSAL && blockIdx.x > blockIdx.y) return;   // fully-masked score blocks

    const int bz = blockIdx.z;
    A += (size_t)bz * sA;
    B += (size_t)bz * sB;
    size_t cOff;
    if (PV) cOff = (size_t)(bz / H_) * S_ * ldc + (size_t)(bz % H_) * VHD_;
    else    cOff = (size_t)bz * sC;

    const int Keff = PV ? min(K, (int)(blockIdx.y + 1) * GBM) : K;
    const int nt = Keff / GBK;

    __shared__ uint32_t As[2][GBK][LDW];
    __shared__ uint32_t Bs[2][GBK][LDW];

    const int tid  = threadIdx.x;
    const int lane = tid & 31;
    const int g    = lane >> 2;
    const int tig  = lane & 3;
    const int wid  = tid >> 5;
    const int wm   = wid & 1;     // 2 warps along M
    const int wn   = wid >> 1;    // 4 warps along N

    // ----- global loaders -----
    // A: [BM x BK] -> As[k][m] (transposed scalar stores)
    const int am = tid >> 1;
    const int ak = (tid & 1) << 3;
    const float* Ap = A + (size_t)(blockIdx.y * GBM + am) * lda + ak;

    // B (NN): [BK x BN] -> Bs[k][n] (direct float4)
    const int br = tid >> 5;                 // 0..7 (and +8)
    const int bc = (tid & 31) << 2;          // 0..124
    // B (TB): [BN x BK] rows -> Bs[k][n] (transposed scalar stores)
    const int bn = tid >> 1;
    const int bk = (tid & 1) << 3;

    const float* Bp;
    bool bValid;
    if (TB) {
        bValid = (blockIdx.x * GBN + bn) < N;
        Bp = B + (size_t)(blockIdx.x * GBN + bn) * ldb + bk;
    } else {
        bValid = (blockIdx.x * GBN + bc) < N;
        Bp = B + (size_t)br * ldb + blockIdx.x * GBN + bc;
    }

    float4 av0, av1, bv0, bv1;
    const float4 z4 = make_float4(0.f, 0.f, 0.f, 0.f);

    auto loadG = [&](int k0) {
        av0 = *(const float4*)(Ap + k0);
        av1 = *(const float4*)(Ap + k0 + 4);
        if (TB) {
            bv0 = bValid ? *(const float4*)(Bp + k0)     : z4;
            bv1 = bValid ? *(const float4*)(Bp + k0 + 4) : z4;
        } else {
            bv0 = bValid ? *(const float4*)(Bp + (size_t)k0 * ldb)       : z4;
            bv1 = bValid ? *(const float4*)(Bp + (size_t)(k0 + 8) * ldb) : z4;
        }
    };
    auto storeS = [&](int buf) {
        As[buf][ak + 0][am] = f2tf32(av0.x);
        As[buf][ak + 1][am] = f2tf32(av0.y);
        As[buf][ak + 2][am] = f2tf32(av0.z);
        As[buf][ak + 3][am] = f2tf32(av0.w);
        As[buf][ak + 4][am] = f2tf32(av1.x);
        As[buf][ak + 5][am] = f2tf32(av1.y);
        As[buf][ak + 6][am] = f2tf32(av1.z);
        As[buf][ak + 7][am] = f2tf32(av1.w);
        if (TB) {
            Bs[buf][bk + 0][bn] = f2tf32(bv0.x);
            Bs[buf][bk + 1][bn] = f2tf32(bv0.y);
            Bs[buf][bk + 2][bn] = f2tf32(bv0.z);
            Bs[buf][bk + 3][bn] = f2tf32(bv0.w);
            Bs[buf][bk + 4][bn] = f2tf32(bv1.x);
            Bs[buf][bk + 5][bn] = f2tf32(bv1.y);
            Bs[buf][bk + 6][bn] = f2tf32(bv1.z);
            Bs[buf][bk + 7][bn] = f2tf32(bv1.w);
        } else {
            Bs[buf][br    ][bc + 0] = f2tf32(bv0.x);
            Bs[buf][br    ][bc + 1] = f2tf32(bv0.y);
            Bs[buf][br    ][bc + 2] = f2tf32(bv0.z);
            Bs[buf][br    ][bc + 3] = f2tf32(bv0.w);
            Bs[buf][br + 8][bc + 0] = f2tf32(bv1.x);
            Bs[buf][br + 8][bc + 1] = f2tf32(bv1.y);
            Bs[buf][br + 8][bc + 2] = f2tf32(bv1.z);
            Bs[buf][br + 8][bc + 3] = f2tf32(bv1.w);
        }
    };

    float acc[4][4][4];
    #pragma unroll
    for (int i = 0; i < 4; i++)
        #pragma unroll
        for (int j = 0; j < 4; j++)
            #pragma unroll
            for (int r = 0; r < 4; r++) acc[i][j][r] = 0.f;

    // prologue
    loadG(0);
    storeS(0);
    __syncthreads();

    for (int t = 0; t < nt; t++) {
        const int buf = t & 1;
        if (t + 1 < nt) loadG((t + 1) * GBK);

        #pragma unroll
        for (int ks = 0; ks < 2; ks++) {
            const int kb = ks * 8;
            uint32_t afr[4][4], bfr[4][2];
            #pragma unroll
            for (int fm = 0; fm < 4; fm++) {
                const int m = wm * 64 + fm * 16 + g;
                afr[fm][0] = As[buf][kb + tig    ][m];
                afr[fm][1] = As[buf][kb + tig    ][m + 8];
                afr[fm][2] = As[buf][kb + tig + 4][m];
                afr[fm][3] = As[buf][kb + tig + 4][m + 8];
            }
            #pragma unroll
            for (int fn = 0; fn < 4; fn++) {
                const int n = wn * 32 + fn * 8 + g;
                bfr[fn][0] = Bs[buf][kb + tig    ][n];
                bfr[fn][1] = Bs[buf][kb + tig + 4][n];
            }
            #pragma unroll
            for (int fm = 0; fm < 4; fm++)
                #pragma unroll
                for (int fn = 0; fn < 4; fn++)
                    mma_tf32(acc[fm][fn], afr[fm], bfr[fn]);
        }

        if (t + 1 < nt) storeS(buf ^ 1);
        __syncthreads();
    }

    // epilogue
    #pragma unroll
    for (int fm = 0; fm < 4; fm++) {
        #pragma unroll
        for (int fn = 0; fn < 4; fn++) {
            const int row = blockIdx.y * GBM + wm * 64 + fm * 16 + g;
            const int col = blockIdx.x * GBN + wn * 32 + fn * 8 + tig * 2;
            if (col < N) {
                float2 o0 = make_float2(acc[fm][fn][0] * alpha, acc[fm][fn][1] * alpha);
                float2 o1 = make_float2(acc[fm][fn][2] * alpha, acc[fm][fn][3] * alpha);
                *(float2*)&C[cOff + (size_t)row * ldc + col]       = o0;
                *(float2*)&C[cOff + (size_t)(row + 8) * ldc + col] = o1;
            }
        }
    }
}

// ---------------- block reductions ----------------
__device__ __forceinline__ float block_reduce_max(float v, float* sbuf) {
    int tid = threadIdx.x;
    sbuf[tid] = v; __syncthreads();
    #pragma unroll
    for (int s = 128; s > 0; s >>= 1) {
        if (tid < s) sbuf[tid] = fmaxf(sbuf[tid], sbuf[tid + s]);
        __syncthreads();
    }
    float r = sbuf[0]; __syncthreads();
    return r;
}
__device__ __forceinline__ float block_reduce_sum(float v, float* sbuf) {
    int tid = threadIdx.x;
    sbuf[tid] = v; __syncthreads();
    #pragma unroll
    for (int s = 128; s > 0; s >>= 1) {
        if (tid < s) sbuf[tid] = sbuf[tid] + sbuf[tid + s];
        __syncthreads();
    }
    float r = sbuf[0]; __syncthreads();
    return r;
}

// ---------------- rmsnorm ----------------
__global__ __launch_bounds__(256) void rmsnorm_kernel(const float* __restrict__ x,
                                                      const float* __restrict__ w,
                                                      float* __restrict__ y,
                                                      int n, int si, int so)
{
    __shared__ float sbuf[256];
    const size_t row = blockIdx.x;
    const float* xr = x + row * si;
    float acc = 0.f;
    for (int j = threadIdx.x; j < n; j += 256) { float v = xr[j]; acc += v * v; }
    float tot = block_reduce_sum(acc, sbuf);
    float scale = rsqrtf(tot / (float)n + EPS_);
    float* yr = y + row * so;
    for (int j = threadIdx.x; j < n; j += 256) yr[j] = xr[j] * scale * w[j];
}

// ---------------- RoPE + assembly ----------------
__device__ __forceinline__ float rope_val(const float* pair_base, int drel, float pos) {
    int j = drel >> 1;
    float inv = powf(10000.f, -((float)(2 * j)) / 64.f);
    float ang = pos * inv;
    float c = cosf(ang), s = sinf(ang);
    float ev = pair_base[2*j], ov = pair_base[2*j + 1];
    return ((drel & 1) == 0) ? (ev * c - ov * s) : (ov * c + ev * s);
}

__global__ void build_q(const int* __restrict__ pos) {
    int idx = blockIdx.x * blockDim.x + threadIdx.x;
    if (idx >= BH_ * S_ * QKD_) return;
    int d  = idx % QKD_;
    int r  = idx / QKD_;
    int s  = r % S_;
    int bh = r / S_;
    int b = bh / H_, h = bh % H_;
    int tok = b * S_ + s;
    const float* src = g_q + (size_t)tok * (H_*QKD_) + h * QKD_;
    float v;
    if (d < NOPE_) v = src[d];
    else           v = rope_val(src + NOPE_, d - NOPE_, (float)pos[tok]);
    g_Qf[idx] = v;
}

__global__ void build_k(const int* __restrict__ pos) {
    int idx = blockIdx.x * blockDim.x + threadIdx.x;
    if (idx >= BH_ * S_ * QKD_) return;
    int d  = idx % QKD_;
    int r  = idx / QKD_;
    int s  = r % S_;
    int bh = r / S_;
    int b = bh / H_, h = bh % H_;
    int tok = b * S_ + s;
    float v;
    if (d < NOPE_) v = g_kv[(size_t)tok * (H_*(NOPE_+VHD_)) + h * (NOPE_+VHD_) + d];
    else           v = rope_val(g_kvc + (size_t)tok * (KVR_+ROPE_) + KVR_,
                                d - NOPE_, (float)pos[tok]);
    g_Kf[idx] = v;
}

__global__ void build_v() {
    int idx = blockIdx.x * blockDim.x + threadIdx.x;
    if (idx >= BH_ * S_ * VHD_) return;
    int d  = idx % VHD_;
    int r  = idx / VHD_;
    int s  = r % S_;
    int bh = r / S_;
    int b = bh / H_, h = bh % H_;
    int tok = b * S_ + s;
    g_Vf[idx] = g_kv[(size_t)tok * (H_*(NOPE_+VHD_)) + h * (NOPE_+VHD_) + NOPE_ + d];
}

// ---------------- causal softmax ----------------
__global__ __launch_bounds__(256) void softmax_causal() {
    __shared__ float sbuf[256];
    const int row = blockIdx.x;
    const int q = row % S_;
    float* p = g_Sc + (size_t)row * S_;
    const int n = q + 1;

    float m = -INFINITY;
    for (int j = threadIdx.x; j < n; j += 256) m = fmaxf(m, p[j]);
    m = block_reduce_max(m, sbuf);

    float acc = 0.f;
    for (int j = threadIdx.x; j < n; j += 256) {
        float e = expf(p[j] - m);
        p[j] = e;
        acc += e;
    }
    float tot = block_reduce_sum(acc, sbuf);
    float inv = 1.f / tot;
    for (int j = threadIdx.x; j < n; j += 256) p[j] *= inv;
    for (int j = n + threadIdx.x; j < S_; j += 256) p[j] = 0.f;
}

// ---------------- launcher ----------------
extern "C" void kernel_launch(void* const* d_in, const int* in_sizes, int n_in,
                              void* d_out, int out_size)
{
    const float* hs    = (const float*)d_in[0];
    const float* Wq_a  = (const float*)d_in[1];
    const float* q_ln  = (const float*)d_in[2];
    const float* Wq_b  = (const float*)d_in[3];
    const float* Wkv_a = (const float*)d_in[4];
    const float* kv_ln = (const float*)d_in[5];
    const float* Wkv_b = (const float*)d_in[6];
    const float* Wo    = (const float*)d_in[7];
    const int*   pos   = (const int*)  d_in[8];
    float* out = (float*)d_out;

    float *p_qa, *p_q, *p_kvc, *p_kvn, *p_kv, *p_ctx, *p_Qf, *p_Kf, *p_Vf, *p_Sc;
    cudaGetSymbolAddress((void**)&p_qa,  g_qa);
    cudaGetSymbolAddress((void**)&p_q,   g_q);
    cudaGetSymbolAddress((void**)&p_kvc, g_kvc);
    cudaGetSymbolAddress((void**)&p_kvn, g_kvn);
    cudaGetSymbolAddress((void**)&p_kv,  g_kv);
    cudaGetSymbolAddress((void**)&p_ctx, g_ctx);
    cudaGetSymbolAddress((void**)&p_Qf,  g_Qf);
    cudaGetSymbolAddress((void**)&p_Kf,  g_Kf);
    cudaGetSymbolAddress((void**)&p_Vf,  g_Vf);
    cudaGetSymbolAddress((void**)&p_Sc,  g_Sc);

    // q path
    mma_gemm<false,false,false><<<dim3(QR_/GBN, TOK_/GBM, 1), 256>>>(
        hs, Wq_a, p_qa, TOK_, QR_, IN_, IN_, QR_, QR_, 0, 0, 0, 1.f);
    rmsnorm_kernel<<<TOK_, 256>>>(p_qa, q_ln, p_qa, QR_, QR_, QR_);
    mma_gemm<false,false,false><<<dim3((H_*QKD_)/GBN, TOK_/GBM, 1), 256>>>(
        p_qa, Wq_b, p_q, TOK_, H_*QKD_, QR_, QR_, H_*QKD_, H_*QKD_, 0, 0, 0, 1.f);

    // kv path
    mma_gemm<false,false,false><<<dim3((KVR_+ROPE_+GBN-1)/GBN, TOK_/GBM, 1), 256>>>(
        hs, Wkv_a, p_kvc, TOK_, KVR_+ROPE_, IN_, IN_, KVR_+ROPE_, KVR_+ROPE_, 0, 0, 0, 1.f);
    rmsnorm_kernel<<<TOK_, 256>>>(p_kvc, kv_ln, p_kvn, KVR_, KVR_+ROPE_, KVR_);
    mma_gemm<false,false,false><<<dim3((H_*(NOPE_+VHD_))/GBN, TOK_/GBM, 1), 256>>>(
        p_kvn, Wkv_b, p_kv, TOK_, H_*(NOPE_+VHD_), KVR_, KVR_,
        H_*(NOPE_+VHD_), H_*(NOPE_+VHD_), 0, 0, 0, 1.f);

    // assemble Q/K/V
    int nq = BH_ * S_ * QKD_;
    build_q<<<(nq + 255) / 256, 256>>>(pos);
    build_k<<<(nq + 255) / 256, 256>>>(pos);
    int nv = BH_ * S_ * VHD_;
    build_v<<<(nv + 255) / 256, 256>>>();

    // attention: scores = scale * Qf @ Kf^T (batched, causal block-skip)
    float scale = 1.f / sqrtf((float)QKD_);
    mma_gemm<true,true,false><<<dim3(S_/GBN, S_/GBM, BH_), 256>>>(
        p_Qf, p_Kf, p_Sc, S_, S_, QKD_, QKD_, QKD_, S_,
        (size_t)S_*QKD_, (size_t)S_*QKD_, (size_t)S_*S_, scale);

    softmax_causal<<<BH_ * S_, 256>>>();

    // PV: ctx = attn @ V (batched, causal K-limit, strided output into [tok][2048])
    mma_gemm<false,false,true><<<dim3(1, S_/GBM, BH_), 256>>>(
        p_Sc, p_Vf, p_ctx, S_, VHD_, S_, S_, VHD_, H_*VHD_,
        (size_t)S_*S_, (size_t)S_*VHD_, 0, 1.f);

    // output projection
    mma_gemm<false,false,false><<<dim3(HID_/GBN, TOK_/GBM, 1), 256>>>(
        p_ctx, Wo, out, TOK_, HID_, HID_, HID_, HID_, HID_, 0, 0, 0, 1.f);
}

// round 3
// speedup vs baseline: 2.5765x; 1.0186x over previous
#include <cuda_runtime.h>
#include <math.h>
#include <stdint.h>

// ---------------- problem constants ----------------
#define B_    2
#define S_    2048
#define HID_  2048
#define IN_   4096
#define H_    16
#define NOPE_ 128
#define ROPE_ 64
#define VHD_  128
#define QKD_  192
#define QR_   1536
#define KVR_  512
#define TOK_  (B_*S_)
#define BH_   (B_*H_)
#define EPS_  1e-6f

// ---------------- scratch ----------------
__device__ float g_qa [TOK_*QR_];
__device__ float g_q  [TOK_*(H_*QKD_)];
__device__ float g_kvc[TOK_*(KVR_+ROPE_)];
__device__ float g_kvn[TOK_*KVR_];
__device__ float g_kv [TOK_*(H_*(NOPE_+VHD_))];
__device__ float g_Qf [BH_*S_*QKD_];
__device__ float g_Kf [BH_*S_*QKD_];
__device__ float g_Vf [BH_*S_*VHD_];
__device__ float g_Sc [(size_t)BH_*S_*S_];
__device__ float g_ctx[TOK_*(H_*VHD_)];
__device__ float g_cos[TOK_*32];
__device__ float g_sin[TOK_*32];

// ---------------- helpers ----------------
__device__ __forceinline__ uint32_t f2tf32(float x) {
    uint32_t u;
    asm("cvt.rna.tf32.f32 %0, %1;" : "=r"(u) : "f"(x));
    return u;
}
__device__ __forceinline__ void mma_tf32(float c[4], const uint32_t a[4], const uint32_t b[2]) {
    asm volatile(
        "mma.sync.aligned.m16n8k8.row.col.f32.tf32.tf32.f32 "
        "{%0,%1,%2,%3}, {%4,%5,%6,%7}, {%8,%9}, {%0,%1,%2,%3};"
        : "+f"(c[0]), "+f"(c[1]), "+f"(c[2]), "+f"(c[3])
        : "r"(a[0]), "r"(a[1]), "r"(a[2]), "r"(a[3]), "r"(b[0]), "r"(b[1]));
}
__device__ __forceinline__ void cp16(uint32_t dst, const void* src, bool pred) {
    int sz = pred ? 16 : 0;
    asm volatile("cp.async.cg.shared.global [%0], [%1], 16, %2;\n"
                 :: "r"(dst), "l"(src), "r"(sz));
}
__device__ __forceinline__ void cp_commit() {
    asm volatile("cp.async.commit_group;\n" ::: "memory");
}
__device__ __forceinline__ void cp_wait1() {
    asm volatile("cp.async.wait_group 1;\n" ::: "memory");
}

// ---------------- tf32 tensor-core GEMM, cp.async 3-stage pipeline ----------------
// C[M,N] = alpha * A[M,K] @ op(B);  op(B) = B[K,N] (TB=0) or B[N,K]^T (TB=1)
// Tiles 128x128, BK=16, 8 warps each 64x32 via 4x4 m16n8k8.
#define GBM 128
#define GBN 128
#define GBK 16
#define STAGES 3
#define A_LDK 20     // 16 + 4 pad words: conflict-free (g*20+tig) lane banks
#define B_LDN 136    // 128 + 8 pad words: conflict-free (tig*8+g) lane banks

#define A_STG (GBM*A_LDK)          // words per A stage
#define BNN_STG (GBK*B_LDN)        // words per B stage (NN)
#define BTB_STG (GBN*A_LDK)        // words per B stage (TB)

template<bool TB, bool CAUSAL, bool PV>
__global__ __launch_bounds__(256) void mma_gemm(
    const float* __restrict__ A, const float* __restrict__ B, float* __restrict__ C,
    int M, int N, int K, int lda, int ldb, int ldc,
    size_t sA, size_t sB, size_t sC, float alpha)
{
    if (CAUSAL && blockIdx.x > blockIdx.y) return;

    extern __shared__ float smem[];
    float* Asm = smem;
    float* Bsm = smem + STAGES * A_STG;
    const uint32_t sA32 = (uint32_t)__cvta_generic_to_shared(Asm);
    const uint32_t sB32 = (uint32_t)__cvta_generic_to_shared(Bsm);

    const int bz = blockIdx.z;
    A += (size_t)bz * sA;
    B += (size_t)bz * sB;
    size_t cOff;
    if (PV) cOff = (size_t)(bz / H_) * S_ * ldc + (size_t)(bz % H_) * VHD_;
    else    cOff = (size_t)bz * sC;

    const int Keff = PV ? min(K, (int)(blockIdx.y + 1) * GBM) : K;
    const int nt = Keff / GBK;

    const int tid  = threadIdx.x;
    const int lane = tid & 31;
    const int g    = lane >> 2;
    const int tig  = lane & 3;
    const int wid  = tid >> 5;
    const int wm   = wid & 1;
    const int wn   = wid >> 1;

    // ---- loader indices ----
    // A: thread t -> row=t>>1, k=(t&1)*8, two 16B chunks (+0,+4)
    const int a_row = tid >> 1;
    const int a_k   = (tid & 1) << 3;
    const float* Ap = A + (size_t)(blockIdx.y * GBM + a_row) * lda + a_k;
    const uint32_t a_dst0 = sA32 + (uint32_t)(a_row * A_LDK + a_k) * 4u;

    // B
    const float* Bp;
    uint32_t b_dst0;
    bool bv0 = true, bv1 = true;
    if (TB) {
        const int b_n = tid >> 1;
        const int b_k = (tid & 1) << 3;
        bv0 = bv1 = (blockIdx.x * GBN + b_n) < N;
        Bp = B + (size_t)(blockIdx.x * GBN + b_n) * ldb + b_k;
        b_dst0 = sB32 + (uint32_t)(b_n * A_LDK + b_k) * 4u;
    } else {
        const int b_kr = tid >> 4;            // 0..15
        const int b_nc = (tid & 15) << 3;     // 0..120
        bv0 = (blockIdx.x * GBN + b_nc)     < N;
        bv1 = (blockIdx.x * GBN + b_nc + 4) < N;
        Bp = B + (size_t)b_kr * ldb + blockIdx.x * GBN + b_nc;
        b_dst0 = sB32 + (uint32_t)(b_kr * B_LDN + b_nc) * 4u;
    }

    auto load_stage = [&](int st, int k0) {
        uint32_t ad = a_dst0 + (uint32_t)(st * A_STG) * 4u;
        const float* as = Ap + k0;
        cp16(ad,      as,     true);
        cp16(ad + 16, as + 4, true);
        if (TB) {
            uint32_t bd = b_dst0 + (uint32_t)(st * BTB_STG) * 4u;
            const float* bs = Bp + k0;
            cp16(bd,      bs,     bv0);
            cp16(bd + 16, bs + 4, bv1);
        } else {
            uint32_t bd = b_dst0 + (uint32_t)(st * BNN_STG) * 4u;
            const float* bs = Bp + (size_t)k0 * ldb;
            cp16(bd,      bs,     bv0);
            cp16(bd + 16, bs + 4, bv1);
        }
    };

    float acc[4][4][4];
    #pragma unroll
    for (int i = 0; i < 4; i++)
        #pragma unroll
        for (int j = 0; j < 4; j++)
            #pragma unroll
            for (int r = 0; r < 4; r++) acc[i][j][r] = 0.f;

    // prologue: stages 0,1
    load_stage(0, 0);
    cp_commit();
    if (nt > 1) load_stage(1, GBK);
    cp_commit();

    for (int t = 0; t < nt; t++) {
        cp_wait1();
        __syncthreads();

        const int tn = t + STAGES - 1;
        if (tn < nt) load_stage(tn % STAGES, tn * GBK);
        cp_commit();

        const float* Ab = Asm + (t % STAGES) * A_STG;
        const float* Bb = TB ? (Bsm + (t % STAGES) * BTB_STG)
                             : (Bsm + (t % STAGES) * BNN_STG);

        #pragma unroll
        for (int ks = 0; ks < 2; ks++) {
            const int kb = ks * 8;
            uint32_t afr[4][4], bfr[4][2];
            #pragma unroll
            for (int fm = 0; fm < 4; fm++) {
                const int m = wm * 64 + fm * 16 + g;
                afr[fm][0] = f2tf32(Ab[(size_t)m       * A_LDK + kb + tig]);
                afr[fm][1] = f2tf32(Ab[(size_t)(m + 8) * A_LDK + kb + tig]);
                afr[fm][2] = f2tf32(Ab[(size_t)m       * A_LDK + kb + tig + 4]);
                afr[fm][3] = f2tf32(Ab[(size_t)(m + 8) * A_LDK + kb + tig + 4]);
            }
            #pragma unroll
            for (int fn = 0; fn < 4; fn++) {
                const int n = wn * 32 + fn * 8 + g;
                if (TB) {
                    bfr[fn][0] = f2tf32(Bb[(size_t)n * A_LDK + kb + tig]);
                    bfr[fn][1] = f2tf32(Bb[(size_t)n * A_LDK + kb + tig + 4]);
                } else {
                    bfr[fn][0] = f2tf32(Bb[(size_t)(kb + tig)     * B_LDN + n]);
                    bfr[fn][1] = f2tf32(Bb[(size_t)(kb + tig + 4) * B_LDN + n]);
                }
            }
            #pragma unroll
            for (int fm = 0; fm < 4; fm++)
                #pragma unroll
                for (int fn = 0; fn < 4; fn++)
                    mma_tf32(acc[fm][fn], afr[fm], bfr[fn]);
        }
    }

    // epilogue
    #pragma unroll
    for (int fm = 0; fm < 4; fm++) {
        #pragma unroll
        for (int fn = 0; fn < 4; fn++) {
            const int row = blockIdx.y * GBM + wm * 64 + fm * 16 + g;
            const int col = blockIdx.x * GBN + wn * 32 + fn * 8 + tig * 2;
            if (col < N) {
                float2 o0 = make_float2(acc[fm][fn][0] * alpha, acc[fm][fn][1] * alpha);
                float2 o1 = make_float2(acc[fm][fn][2] * alpha, acc[fm][fn][3] * alpha);
                *(float2*)&C[cOff + (size_t)row * ldc + col]       = o0;
                *(float2*)&C[cOff + (size_t)(row + 8) * ldc + col] = o1;
            }
        }
    }
}

#define SMEM_NN ((STAGES*A_STG + STAGES*BNN_STG) * 4)
#define SMEM_TB ((STAGES*A_STG + STAGES*BTB_STG) * 4)

// ---------------- block reductions ----------------
__device__ __forceinline__ float block_reduce_max(float v, float* sbuf) {
    int tid = threadIdx.x;
    sbuf[tid] = v; __syncthreads();
    #pragma unroll
    for (int s = 128; s > 0; s >>= 1) {
        if (tid < s) sbuf[tid] = fmaxf(sbuf[tid], sbuf[tid + s]);
        __syncthreads();
    }
    float r = sbuf[0]; __syncthreads();
    return r;
}
__device__ __forceinline__ float block_reduce_sum(float v, float* sbuf) {
    int tid = threadIdx.x;
    sbuf[tid] = v; __syncthreads();
    #pragma unroll
    for (int s = 128; s > 0; s >>= 1) {
        if (tid < s) sbuf[tid] = sbuf[tid] + sbuf[tid + s];
        __syncthreads();
    }
    float r = sbuf[0]; __syncthreads();
    return r;
}

// ---------------- rmsnorm ----------------
__global__ __launch_bounds__(256) void rmsnorm_kernel(const float* __restrict__ x,
                                                      const float* __restrict__ w,
                                                      float* __restrict__ y,
                                                      int n, int si, int so)
{
    __shared__ float sbuf[256];
    const size_t row = blockIdx.x;
    const float* xr = x + row * si;
    float acc = 0.f;
    for (int j = threadIdx.x; j < n; j += 256) { float v = xr[j]; acc += v * v; }
    float tot = block_reduce_sum(acc, sbuf);
    float scale = rsqrtf(tot / (float)n + EPS_);
    float* yr = y + row * so;
    for (int j = threadIdx.x; j < n; j += 256) yr[j] = xr[j] * scale * w[j];
}

// ---------------- RoPE table + assembly ----------------
__global__ void build_cs(const int* __restrict__ pos) {
    int idx = blockIdx.x * blockDim.x + threadIdx.x;
    if (idx >= TOK_ * 32) return;
    int j = idx & 31, tok = idx >> 5;
    float inv = powf(10000.f, -((float)(2 * j)) / 64.f);
    float ang = (float)pos[tok] * inv;
    g_cos[idx] = cosf(ang);
    g_sin[idx] = sinf(ang);
}

__device__ __forceinline__ float rope_val(const float* pair_base, int drel, int tok) {
    int j = drel >> 1;
    float c = g_cos[tok * 32 + j], s = g_sin[tok * 32 + j];
    float ev = pair_base[2*j], ov = pair_base[2*j + 1];
    return ((drel & 1) == 0) ? (ev * c - ov * s) : (ov * c + ev * s);
}

__global__ void build_q() {
    int idx = blockIdx.x * blockDim.x + threadIdx.x;
    if (idx >= BH_ * S_ * QKD_) return;
    int d  = idx % QKD_;
    int r  = idx / QKD_;
    int s  = r % S_;
    int bh = r / S_;
    int b = bh / H_, h = bh % H_;
    int tok = b * S_ + s;
    const float* src = g_q + (size_t)tok * (H_*QKD_) + h * QKD_;
    float v;
    if (d < NOPE_) v = src[d];
    else           v = rope_val(src + NOPE_, d - NOPE_, tok);
    g_Qf[idx] = v;
}

__global__ void build_k() {
    int idx = blockIdx.x * blockDim.x + threadIdx.x;
    if (idx >= BH_ * S_ * QKD_) return;
    int d  = idx % QKD_;
    int r  = idx / QKD_;
    int s  = r % S_;
    int bh = r / S_;
    int b = bh / H_, h = bh % H_;
    int tok = b * S_ + s;
    float v;
    if (d < NOPE_) v = g_kv[(size_t)tok * (H_*(NOPE_+VHD_)) + h * (NOPE_+VHD_) + d];
    else           v = rope_val(g_kvc + (size_t)tok * (KVR_+ROPE_) + KVR_, d - NOPE_, tok);
    g_Kf[idx] = v;
}

__global__ void build_v() {
    int idx = blockIdx.x * blockDim.x + threadIdx.x;
    if (idx >= BH_ * S_ * VHD_) return;
    int d  = idx % VHD_;
    int r  = idx / VHD_;
    int s  = r % S_;
    int bh = r / S_;
    int b = bh / H_, h = bh % H_;
    int tok = b * S_ + s;
    g_Vf[idx] = g_kv[(size_t)tok * (H_*(NOPE_+VHD_)) + h * (NOPE_+VHD_) + NOPE_ + d];
}

// ---------------- causal softmax ----------------
__global__ __launch_bounds__(256) void softmax_causal() {
    __shared__ float sbuf[256];
    const int row = blockIdx.x;
    const int q = row % S_;
    float* p = g_Sc + (size_t)row * S_;
    const int n = q + 1;

    float m = -INFINITY;
    for (int j = threadIdx.x; j < n; j += 256) m = fmaxf(m, p[j]);
    m = block_reduce_max(m, sbuf);

    float acc = 0.f;
    for (int j = threadIdx.x; j < n; j += 256) {
        float e = expf(p[j] - m);
        p[j] = e;
        acc += e;
    }
    float tot = block_reduce_sum(acc, sbuf);
    float inv = 1.f / tot;
    for (int j = threadIdx.x; j < n; j += 256) p[j] *= inv;
    for (int j = n + threadIdx.x; j < S_; j += 256) p[j] = 0.f;
}

// ---------------- launcher ----------------
extern "C" void kernel_launch(void* const* d_in, const int* in_sizes, int n_in,
                              void* d_out, int out_size)
{
    const float* hs    = (const float*)d_in[0];
    const float* Wq_a  = (const float*)d_in[1];
    const float* q_ln  = (const float*)d_in[2];
    const float* Wq_b  = (const float*)d_in[3];
    const float* Wkv_a = (const float*)d_in[4];
    const float* kv_ln = (const float*)d_in[5];
    const float* Wkv_b = (const float*)d_in[6];
    const float* Wo    = (const float*)d_in[7];
    const int*   pos   = (const int*)  d_in[8];
    float* out = (float*)d_out;

    float *p_qa, *p_q, *p_kvc, *p_kvn, *p_kv, *p_ctx, *p_Qf, *p_Kf, *p_Vf, *p_Sc;
    cudaGetSymbolAddress((void**)&p_qa,  g_qa);
    cudaGetSymbolAddress((void**)&p_q,   g_q);
    cudaGetSymbolAddress((void**)&p_kvc, g_kvc);
    cudaGetSymbolAddress((void**)&p_kvn, g_kvn);
    cudaGetSymbolAddress((void**)&p_kv,  g_kv);
    cudaGetSymbolAddress((void**)&p_ctx, g_ctx);
    cudaGetSymbolAddress((void**)&p_Qf,  g_Qf);
    cudaGetSymbolAddress((void**)&p_Kf,  g_Kf);
    cudaGetSymbolAddress((void**)&p_Vf,  g_Vf);
    cudaGetSymbolAddress((void**)&p_Sc,  g_Sc);

    static bool attr_done = false;
    if (!attr_done) {
        cudaFuncSetAttribute(mma_gemm<false,false,false>,
                             cudaFuncAttributeMaxDynamicSharedMemorySize, SMEM_NN);
        cudaFuncSetAttribute(mma_gemm<true,true,false>,
                             cudaFuncAttributeMaxDynamicSharedMemorySize, SMEM_TB);
        cudaFuncSetAttribute(mma_gemm<false,false,true>,
                             cudaFuncAttributeMaxDynamicSharedMemorySize, SMEM_NN);
        attr_done = true;
    }

    // q path
    mma_gemm<false,false,false><<<dim3(QR_/GBN, TOK_/GBM, 1), 256, SMEM_NN>>>(
        hs, Wq_a, p_qa, TOK_, QR_, IN_, IN_, QR_, QR_, 0, 0, 0, 1.f);
    rmsnorm_kernel<<<TOK_, 256>>>(p_qa, q_ln, p_qa, QR_, QR_, QR_);
    mma_gemm<false,false,false><<<dim3((H_*QKD_)/GBN, TOK_/GBM, 1), 256, SMEM_NN>>>(
        p_qa, Wq_b, p_q, TOK_, H_*QKD_, QR_, QR_, H_*QKD_, H_*QKD_, 0, 0, 0, 1.f);

    // kv path
    mma_gemm<false,false,false><<<dim3((KVR_+ROPE_+GBN-1)/GBN, TOK_/GBM, 1), 256, SMEM_NN>>>(
        hs, Wkv_a, p_kvc, TOK_, KVR_+ROPE_, IN_, IN_, KVR_+ROPE_, KVR_+ROPE_, 0, 0, 0, 1.f);
    rmsnorm_kernel<<<TOK_, 256>>>(p_kvc, kv_ln, p_kvn, KVR_, KVR_+ROPE_, KVR_);
    mma_gemm<false,false,false><<<dim3((H_*(NOPE_+VHD_))/GBN, TOK_/GBM, 1), 256, SMEM_NN>>>(
        p_kvn, Wkv_b, p_kv, TOK_, H_*(NOPE_+VHD_), KVR_, KVR_,
        H_*(NOPE_+VHD_), H_*(NOPE_+VHD_), 0, 0, 0, 1.f);

    // RoPE table + assemble Q/K/V
    build_cs<<<(TOK_*32 + 255)/256, 256>>>(pos);
    int nq = BH_ * S_ * QKD_;
    build_q<<<(nq + 255) / 256, 256>>>();
    build_k<<<(nq + 255) / 256, 256>>>();
    int nv = BH_ * S_ * VHD_;
    build_v<<<(nv + 255) / 256, 256>>>();

    // scores = scale * Qf @ Kf^T (batched, causal block-skip)
    float scale = 1.f / sqrtf((float)QKD_);
    mma_gemm<true,true,false><<<dim3(S_/GBN, S_/GBM, BH_), 256, SMEM_TB>>>(
        p_Qf, p_Kf, p_Sc, S_, S_, QKD_, QKD_, QKD_, S_,
        (size_t)S_*QKD_, (size_t)S_*QKD_, (size_t)S_*S_, scale);

    softmax_causal<<<BH_ * S_, 256>>>();

    // PV: ctx = attn @ V (batched, causal K-limit, strided output)
    mma_gemm<false,false,true><<<dim3(1, S_/GBM, BH_), 256, SMEM_NN>>>(
        p_Sc, p_Vf, p_ctx, S_, VHD_, S_, S_, VHD_, H_*VHD_,
        (size_t)S_*S_, (size_t)S_*VHD_, 0, 1.f);

    // output projection
    mma_gemm<false,false,false><<<dim3(HID_/GBN, TOK_/GBM, 1), 256, SMEM_NN>>>(
        p_ctx, Wo, out, TOK_, HID_, HID_, HID_, HID_, HID_, 0, 0, 0, 1.f);
}

// round 4
// speedup vs baseline: 2.7461x; 1.0658x over previous
#include <cuda_runtime.h>
#include <math.h>
#include <stdint.h>

// ---------------- problem constants ----------------
#define B_    2
#define S_    2048
#define HID_  2048
#define IN_   4096
#define H_    16
#define NOPE_ 128
#define ROPE_ 64
#define VHD_  128
#define QKD_  192
#define QR_   1536
#define KVR_  512
#define TOK_  (B_*S_)
#define BH_   (B_*H_)
#define EPS_  1e-6f

// ---------------- scratch ----------------
__device__ float g_qa [TOK_*QR_];
__device__ float g_q  [TOK_*(H_*QKD_)];
__device__ float g_kvc[TOK_*(KVR_+ROPE_)];
__device__ float g_kvn[TOK_*KVR_];
__device__ float g_kv [TOK_*(H_*(NOPE_+VHD_))];
__device__ float g_Qf [BH_*S_*QKD_];
__device__ float g_Kf [BH_*S_*QKD_];
__device__ float g_Vf [BH_*S_*VHD_];
__device__ float g_Sc [(size_t)BH_*S_*S_];
__device__ float g_ctx[TOK_*(H_*VHD_)];
__device__ float g_cos[TOK_*32];
__device__ float g_sin[TOK_*32];

// ---------------- helpers ----------------
__device__ __forceinline__ uint32_t f2tf32(float x) {
    uint32_t u;
    asm("cvt.rna.tf32.f32 %0, %1;" : "=r"(u) : "f"(x));
    return u;
}
__device__ __forceinline__ void mma_tf32(float c[4], const uint32_t a[4], const uint32_t b[2]) {
    asm volatile(
        "mma.sync.aligned.m16n8k8.row.col.f32.tf32.tf32.f32 "
        "{%0,%1,%2,%3}, {%4,%5,%6,%7}, {%8,%9}, {%0,%1,%2,%3};"
        : "+f"(c[0]), "+f"(c[1]), "+f"(c[2]), "+f"(c[3])
        : "r"(a[0]), "r"(a[1]), "r"(a[2]), "r"(a[3]), "r"(b[0]), "r"(b[1]));
}
__device__ __forceinline__ void cp16(uint32_t dst, const void* src, bool pred) {
    int sz = pred ? 16 : 0;
    asm volatile("cp.async.cg.shared.global [%0], [%1], 16, %2;\n"
                 :: "r"(dst), "l"(src), "r"(sz));
}
__device__ __forceinline__ void cp_commit() {
    asm volatile("cp.async.commit_group;\n" ::: "memory");
}
__device__ __forceinline__ void cp_wait1() {
    asm volatile("cp.async.wait_group 1;\n" ::: "memory");
}

// ---------------- tf32 tensor-core GEMM, cp.async 3-stage pipeline ----------------
// C[M,N] = alpha * A[M,K] @ op(B);  op(B) = B[K,N] (TB=0) or B[N,K]^T (TB=1)
// Tiles 128x128, BK=16, 8 warps each 64x32 via 4x4 m16n8k8.
// __launch_bounds__(256, 2): 2 CTAs/SM -> 4 warps/SMSP for latency hiding.
#define GBM 128
#define GBN 128
#define GBK 16
#define STAGES 3
#define A_LDK 20
#define B_LDN 136

#define A_STG (GBM*A_LDK)
#define BNN_STG (GBK*B_LDN)
#define BTB_STG (GBN*A_LDK)

template<bool TB, bool CAUSAL, bool PV>
__global__ __launch_bounds__(256, 2) void mma_gemm(
    const float* __restrict__ A, const float* __restrict__ B, float* __restrict__ C,
    int M, int N, int K, int lda, int ldb, int ldc,
    size_t sA, size_t sB, size_t sC, float alpha)
{
    if (CAUSAL && blockIdx.x > blockIdx.y) return;

    extern __shared__ float smem[];
    float* Asm = smem;
    float* Bsm = smem + STAGES * A_STG;
    const uint32_t sA32 = (uint32_t)__cvta_generic_to_shared(Asm);
    const uint32_t sB32 = (uint32_t)__cvta_generic_to_shared(Bsm);

    const int bz = blockIdx.z;
    A += (size_t)bz * sA;
    B += (size_t)bz * sB;
    size_t cOff;
    if (PV) cOff = (size_t)(bz / H_) * S_ * ldc + (size_t)(bz % H_) * VHD_;
    else    cOff = (size_t)bz * sC;

    const int Keff = PV ? min(K, (int)(blockIdx.y + 1) * GBM) : K;
    const int nt = Keff / GBK;

    const int tid  = threadIdx.x;
    const int lane = tid & 31;
    const int g    = lane >> 2;
    const int tig  = lane & 3;
    const int wid  = tid >> 5;
    const int wm   = wid & 1;
    const int wn   = wid >> 1;

    // ---- loader indices ----
    const int a_row = tid >> 1;
    const int a_k   = (tid & 1) << 3;
    const float* Ap = A + (size_t)(blockIdx.y * GBM + a_row) * lda + a_k;
    const uint32_t a_dst0 = sA32 + (uint32_t)(a_row * A_LDK + a_k) * 4u;

    const float* Bp;
    uint32_t b_dst0;
    bool bv0 = true, bv1 = true;
    if (TB) {
        const int b_n = tid >> 1;
        const int b_k = (tid & 1) << 3;
        bv0 = bv1 = (blockIdx.x * GBN + b_n) < N;
        Bp = B + (size_t)(blockIdx.x * GBN + b_n) * ldb + b_k;
        b_dst0 = sB32 + (uint32_t)(b_n * A_LDK + b_k) * 4u;
    } else {
        const int b_kr = tid >> 4;
        const int b_nc = (tid & 15) << 3;
        bv0 = (blockIdx.x * GBN + b_nc)     < N;
        bv1 = (blockIdx.x * GBN + b_nc + 4) < N;
        Bp = B + (size_t)b_kr * ldb + blockIdx.x * GBN + b_nc;
        b_dst0 = sB32 + (uint32_t)(b_kr * B_LDN + b_nc) * 4u;
    }

    auto load_stage = [&](int st, int k0) {
        uint32_t ad = a_dst0 + (uint32_t)(st * A_STG) * 4u;
        const float* as = Ap + k0;
        cp16(ad,      as,     true);
        cp16(ad + 16, as + 4, true);
        if (TB) {
            uint32_t bd = b_dst0 + (uint32_t)(st * BTB_STG) * 4u;
            const float* bs = Bp + k0;
            cp16(bd,      bs,     bv0);
            cp16(bd + 16, bs + 4, bv1);
        } else {
            uint32_t bd = b_dst0 + (uint32_t)(st * BNN_STG) * 4u;
            const float* bs = Bp + (size_t)k0 * ldb;
            cp16(bd,      bs,     bv0);
            cp16(bd + 16, bs + 4, bv1);
        }
    };

    float acc[4][4][4];
    #pragma unroll
    for (int i = 0; i < 4; i++)
        #pragma unroll
        for (int j = 0; j < 4; j++)
            #pragma unroll
            for (int r = 0; r < 4; r++) acc[i][j][r] = 0.f;

    load_stage(0, 0);
    cp_commit();
    if (nt > 1) load_stage(1, GBK);
    cp_commit();

    for (int t = 0; t < nt; t++) {
        cp_wait1();
        __syncthreads();

        const int tn = t + STAGES - 1;
        if (tn < nt) load_stage(tn % STAGES, tn * GBK);
        cp_commit();

        const float* Ab = Asm + (t % STAGES) * A_STG;
        const float* Bb = TB ? (Bsm + (t % STAGES) * BTB_STG)
                             : (Bsm + (t % STAGES) * BNN_STG);

        #pragma unroll
        for (int ks = 0; ks < 2; ks++) {
            const int kb = ks * 8;
            uint32_t afr[4][4], bfr[4][2];
            #pragma unroll
            for (int fm = 0; fm < 4; fm++) {
                const int m = wm * 64 + fm * 16 + g;
                afr[fm][0] = f2tf32(Ab[(size_t)m       * A_LDK + kb + tig]);
                afr[fm][1] = f2tf32(Ab[(size_t)(m + 8) * A_LDK + kb + tig]);
                afr[fm][2] = f2tf32(Ab[(size_t)m       * A_LDK + kb + tig + 4]);
                afr[fm][3] = f2tf32(Ab[(size_t)(m + 8) * A_LDK + kb + tig + 4]);
            }
            #pragma unroll
            for (int fn = 0; fn < 4; fn++) {
                const int n = wn * 32 + fn * 8 + g;
                if (TB) {
                    bfr[fn][0] = f2tf32(Bb[(size_t)n * A_LDK + kb + tig]);
                    bfr[fn][1] = f2tf32(Bb[(size_t)n * A_LDK + kb + tig + 4]);
                } else {
                    bfr[fn][0] = f2tf32(Bb[(size_t)(kb + tig)     * B_LDN + n]);
                    bfr[fn][1] = f2tf32(Bb[(size_t)(kb + tig + 4) * B_LDN + n]);
                }
            }
            #pragma unroll
            for (int fm = 0; fm < 4; fm++)
                #pragma unroll
                for (int fn = 0; fn < 4; fn++)
                    mma_tf32(acc[fm][fn], afr[fm], bfr[fn]);
        }
    }

    // epilogue
    #pragma unroll
    for (int fm = 0; fm < 4; fm++) {
        #pragma unroll
        for (int fn = 0; fn < 4; fn++) {
            const int row = blockIdx.y * GBM + wm * 64 + fm * 16 + g;
            const int col = blockIdx.x * GBN + wn * 32 + fn * 8 + tig * 2;
            if (col < N) {
                float2 o0 = make_float2(acc[fm][fn][0] * alpha, acc[fm][fn][1] * alpha);
                float2 o1 = make_float2(acc[fm][fn][2] * alpha, acc[fm][fn][3] * alpha);
                *(float2*)&C[cOff + (size_t)row * ldc + col]       = o0;
                *(float2*)&C[cOff + (size_t)(row + 8) * ldc + col] = o1;
            }
        }
    }
}

#define SMEM_NN ((STAGES*A_STG + STAGES*BNN_STG) * 4)
#define SMEM_TB ((STAGES*A_STG + STAGES*BTB_STG) * 4)

// ---------------- block reductions ----------------
__device__ __forceinline__ float block_reduce_max(float v, float* sbuf) {
    int tid = threadIdx.x;
    sbuf[tid] = v; __syncthreads();
    #pragma unroll
    for (int s = 128; s > 0; s >>= 1) {
        if (tid < s) sbuf[tid] = fmaxf(sbuf[tid], sbuf[tid + s]);
        __syncthreads();
    }
    float r = sbuf[0]; __syncthreads();
    return r;
}
__device__ __forceinline__ float block_reduce_sum(float v, float* sbuf) {
    int tid = threadIdx.x;
    sbuf[tid] = v; __syncthreads();
    #pragma unroll
    for (int s = 128; s > 0; s >>= 1) {
        if (tid < s) sbuf[tid] = sbuf[tid] + sbuf[tid + s];
        __syncthreads();
    }
    float r = sbuf[0]; __syncthreads();
    return r;
}

// ---------------- rmsnorm ----------------
__global__ __launch_bounds__(256) void rmsnorm_kernel(const float* __restrict__ x,
                                                      const float* __restrict__ w,
                                                      float* __restrict__ y,
                                                      int n, int si, int so)
{
    __shared__ float sbuf[256];
    const size_t row = blockIdx.x;
    const float* xr = x + row * si;
    float acc = 0.f;
    for (int j = threadIdx.x; j < n; j += 256) { float v = xr[j]; acc += v * v; }
    float tot = block_reduce_sum(acc, sbuf);
    float scale = rsqrtf(tot / (float)n + EPS_);
    float* yr = y + row * so;
    for (int j = threadIdx.x; j < n; j += 256) yr[j] = xr[j] * scale * w[j];
}

// ---------------- RoPE table + assembly ----------------
__global__ void build_cs(const int* __restrict__ pos) {
    int idx = blockIdx.x * blockDim.x + threadIdx.x;
    if (idx >= TOK_ * 32) return;
    int j = idx & 31, tok = idx >> 5;
    float inv = powf(10000.f, -((float)(2 * j)) / 64.f);
    float ang = (float)pos[tok] * inv;
    g_cos[idx] = cosf(ang);
    g_sin[idx] = sinf(ang);
}

__device__ __forceinline__ float rope_val(const float* pair_base, int drel, int tok) {
    int j = drel >> 1;
    float c = g_cos[tok * 32 + j], s = g_sin[tok * 32 + j];
    float ev = pair_base[2*j], ov = pair_base[2*j + 1];
    return ((drel & 1) == 0) ? (ev * c - ov * s) : (ov * c + ev * s);
}

__global__ void build_q() {
    int idx = blockIdx.x * blockDim.x + threadIdx.x;
    if (idx >= BH_ * S_ * QKD_) return;
    int d  = idx % QKD_;
    int r  = idx / QKD_;
    int s  = r % S_;
    int bh = r / S_;
    int b = bh / H_, h = bh % H_;
    int tok = b * S_ + s;
    const float* src = g_q + (size_t)tok * (H_*QKD_) + h * QKD_;
    float v;
    if (d < NOPE_) v = src[d];
    else           v = rope_val(src + NOPE_, d - NOPE_, tok);
    g_Qf[idx] = v;
}

__global__ void build_k() {
    int idx = blockIdx.x * blockDim.x + threadIdx.x;
    if (idx >= BH_ * S_ * QKD_) return;
    int d  = idx % QKD_;
    int r  = idx / QKD_;
    int s  = r % S_;
    int bh = r / S_;
    int b = bh / H_, h = bh % H_;
    int tok = b * S_ + s;
    float v;
    if (d < NOPE_) v = g_kv[(size_t)tok * (H_*(NOPE_+VHD_)) + h * (NOPE_+VHD_) + d];
    else           v = rope_val(g_kvc + (size_t)tok * (KVR_+ROPE_) + KVR_, d - NOPE_, tok);
    g_Kf[idx] = v;
}

__global__ void build_v() {
    int idx = blockIdx.x * blockDim.x + threadIdx.x;
    if (idx >= BH_ * S_ * VHD_) return;
    int d  = idx % VHD_;
    int r  = idx / VHD_;
    int s  = r % S_;
    int bh = r / S_;
    int b = bh / H_, h = bh % H_;
    int tok = b * S_ + s;
    g_Vf[idx] = g_kv[(size_t)tok * (H_*(NOPE_+VHD_)) + h * (NOPE_+VHD_) + NOPE_ + d];
}

// ---------------- causal softmax ----------------
__global__ __launch_bounds__(256) void softmax_causal() {
    __shared__ float sbuf[256];
    const int row = blockIdx.x;
    const int q = row % S_;
    float* p = g_Sc + (size_t)row * S_;
    const int n = q + 1;

    float m = -INFINITY;
    for (int j = threadIdx.x; j < n; j += 256) m = fmaxf(m, p[j]);
    m = block_reduce_max(m, sbuf);

    float acc = 0.f;
    for (int j = threadIdx.x; j < n; j += 256) {
        float e = expf(p[j] - m);
        p[j] = e;
        acc += e;
    }
    float tot = block_reduce_sum(acc, sbuf);
    float inv = 1.f / tot;
    for (int j = threadIdx.x; j < n; j += 256) p[j] *= inv;
    for (int j = n + threadIdx.x; j < S_; j += 256) p[j] = 0.f;
}

// ---------------- launcher ----------------
extern "C" void kernel_launch(void* const* d_in, const int* in_sizes, int n_in,
                              void* d_out, int out_size)
{
    const float* hs    = (const float*)d_in[0];
    const float* Wq_a  = (const float*)d_in[1];
    const float* q_ln  = (const float*)d_in[2];
    const float* Wq_b  = (const float*)d_in[3];
    const float* Wkv_a = (const float*)d_in[4];
    const float* kv_ln = (const float*)d_in[5];
    const float* Wkv_b = (const float*)d_in[6];
    const float* Wo    = (const float*)d_in[7];
    const int*   pos   = (const int*)  d_in[8];
    float* out = (float*)d_out;

    float *p_qa, *p_q, *p_kvc, *p_kvn, *p_kv, *p_ctx, *p_Qf, *p_Kf, *p_Vf, *p_Sc;
    cudaGetSymbolAddress((void**)&p_qa,  g_qa);
    cudaGetSymbolAddress((void**)&p_q,   g_q);
    cudaGetSymbolAddress((void**)&p_kvc, g_kvc);
    cudaGetSymbolAddress((void**)&p_kvn, g_kvn);
    cudaGetSymbolAddress((void**)&p_kv,  g_kv);
    cudaGetSymbolAddress((void**)&p_ctx, g_ctx);
    cudaGetSymbolAddress((void**)&p_Qf,  g_Qf);
    cudaGetSymbolAddress((void**)&p_Kf,  g_Kf);
    cudaGetSymbolAddress((void**)&p_Vf,  g_Vf);
    cudaGetSymbolAddress((void**)&p_Sc,  g_Sc);

    static bool attr_done = false;
    if (!attr_done) {
        cudaFuncSetAttribute(mma_gemm<false,false,false>,
                             cudaFuncAttributeMaxDynamicSharedMemorySize, SMEM_NN);
        cudaFuncSetAttribute(mma_gemm<true,true,false>,
                             cudaFuncAttributeMaxDynamicSharedMemorySize, SMEM_TB);
        cudaFuncSetAttribute(mma_gemm<false,false,true>,
                             cudaFuncAttributeMaxDynamicSharedMemorySize, SMEM_NN);
        attr_done = true;
    }

    // q path
    mma_gemm<false,false,false><<<dim3(QR_/GBN, TOK_/GBM, 1), 256, SMEM_NN>>>(
        hs, Wq_a, p_qa, TOK_, QR_, IN_, IN_, QR_, QR_, 0, 0, 0, 1.f);
    rmsnorm_kernel<<<TOK_, 256>>>(p_qa, q_ln, p_qa, QR_, QR_, QR_);
    mma_gemm<false,false,false><<<dim3((H_*QKD_)/GBN, TOK_/GBM, 1), 256, SMEM_NN>>>(
        p_qa, Wq_b, p_q, TOK_, H_*QKD_, QR_, QR_, H_*QKD_, H_*QKD_, 0, 0, 0, 1.f);

    // kv path
    mma_gemm<false,false,false><<<dim3((KVR_+ROPE_+GBN-1)/GBN, TOK_/GBM, 1), 256, SMEM_NN>>>(
        hs, Wkv_a, p_kvc, TOK_, KVR_+ROPE_, IN_, IN_, KVR_+ROPE_, KVR_+ROPE_, 0, 0, 0, 1.f);
    rmsnorm_kernel<<<TOK_, 256>>>(p_kvc, kv_ln, p_kvn, KVR_, KVR_+ROPE_, KVR_);
    mma_gemm<false,false,false><<<dim3((H_*(NOPE_+VHD_))/GBN, TOK_/GBM, 1), 256, SMEM_NN>>>(
        p_kvn, Wkv_b, p_kv, TOK_, H_*(NOPE_+VHD_), KVR_, KVR_,
        H_*(NOPE_+VHD_), H_*(NOPE_+VHD_), 0, 0, 0, 1.f);

    // RoPE table + assemble Q/K/V
    build_cs<<<(TOK_*32 + 255)/256, 256>>>(pos);
    int nq = BH_ * S_ * QKD_;
    build_q<<<(nq + 255) / 256, 256>>>();
    build_k<<<(nq + 255) / 256, 256>>>();
    int nv = BH_ * S_ * VHD_;
    build_v<<<(nv + 255) / 256, 256>>>();

    // scores = scale * Qf @ Kf^T (batched, causal block-skip)
    float scale = 1.f / sqrtf((float)QKD_);
    mma_gemm<true,true,false><<<dim3(S_/GBN, S_/GBM, BH_), 256, SMEM_TB>>>(
        p_Qf, p_Kf, p_Sc, S_, S_, QKD_, QKD_, QKD_, S_,
        (size_t)S_*QKD_, (size_t)S_*QKD_, (size_t)S_*S_, scale);

    softmax_causal<<<BH_ * S_, 256>>>();

    // PV: ctx = attn @ V (batched, causal K-limit, strided output)
    mma_gemm<false,false,true><<<dim3(1, S_/GBM, BH_), 256, SMEM_NN>>>(
        p_Sc, p_Vf, p_ctx, S_, VHD_, S_, S_, VHD_, H_*VHD_,
        (size_t)S_*S_, (size_t)S_*VHD_, 0, 1.f);

    // output projection
    mma_gemm<false,false,false><<<dim3(HID_/GBN, TOK_/GBM, 1), 256, SMEM_NN>>>(
        p_ctx, Wo, out, TOK_, HID_, HID_, HID_, HID_, HID_, 0, 0, 0, 1.f);
}